// round 1
// baseline (speedup 1.0000x reference)
#include <cuda_runtime.h>
#include <math.h>

constexpr int NNODE = 10000;
constexpr int NEDGE = 160000;
constexpr int C = 32;
constexpr int H = 64;
constexpr int F_OFF1 = NNODE * C;        // start of l=1 block
constexpr int F_OFF2 = 4 * NNODE * C;    // start of l=2 block
constexpr int F_OFF3 = 9 * NNODE * C;    // start of l=3 block
constexpr int FTOT   = 16 * NNODE * C;   // total f/agg elements

// ---------------- scratch (device globals; no allocation allowed) ----------
__device__ float  g_h [(size_t)NEDGE * H];      // edge hidden (E,64)
__device__ float  g_w [(size_t)NEDGE * 384];    // w_all (E, L*NL*C)
__device__ float  g_ew[(size_t)NEDGE * 128];    // edge weights (E, NL*C)
__device__ float  g_sh[(size_t)NEDGE * 16];     // spherical harmonics (E,16)
__device__ float2 g_geo[NEDGE];                 // (u, pref = env*sqrt(2/RC)/r)
__device__ float  g_f[2][FTOT];                 // node features, double buffered
__device__ float  g_agg[FTOT];                  // per-layer aggregation

__device__ __forceinline__ float siluf(float x) { return x / (1.0f + expf(-x)); }

// layout helper: f/agg element (l, n, m, c) at OFF[l] + (n*d_l + m)*C + c
__device__ __forceinline__ void decode_col(int col, int& l, int& c, int& m,
                                           int& dl, int& off) {
    if (col < 32)       { l = 0; c = col;          m = 0;         dl = 1; off = 0;      }
    else if (col < 128) { l = 1; int q = col - 32;  c = q / 3; m = q - 3 * c; dl = 3; off = F_OFF1; }
    else if (col < 288) { l = 2; int q = col - 128; c = q / 5; m = q - 5 * c; dl = 5; off = F_OFF2; }
    else                { l = 3; int q = col - 288; c = q / 7; m = q - 7 * c; dl = 7; off = F_OFF3; }
}

// ---------------- K1: per-edge geometry + spherical harmonics --------------
__global__ void k_geom(const float* __restrict__ pos, const int* __restrict__ ei) {
    int e = blockIdx.x * 256 + threadIdx.x;
    int s = ei[e], d = ei[NEDGE + e];
    float ax = pos[3 * s], ay = pos[3 * s + 1], az = pos[3 * s + 2];
    float bx = pos[3 * d], by = pos[3 * d + 1], bz = pos[3 * d + 2];
    float vx = bx - ax, vy = by - ay, vz = bz - az;
    float r = sqrtf(vx * vx + vy * vy + vz * vz + 1e-12f);
    float u = fminf(r * (1.0f / 5.0f), 1.0f);
    float env = 0.5f * (cospif(u) + 1.0f);
    g_geo[e] = make_float2(u, env * 0.63245553203f / r);   // sqrt(2/RC)=sqrt(0.4)
    float inv = 1.0f / r;
    float x = vx * inv, y = vy * inv, z = vz * inv;
    float x2 = x * x, y2 = y * y, z2 = z * z;
    float sh[16];
    sh[0] = 1.0f;
    sh[1] = 1.7320508f * x; sh[2] = 1.7320508f * y; sh[3] = 1.7320508f * z;
    sh[4] = 3.87298335f * x * y;
    sh[5] = 3.87298335f * y * z;
    sh[6] = 1.11803399f * (3.0f * z2 - 1.0f);
    sh[7] = 3.87298335f * x * z;
    sh[8] = 1.93649167f * (x2 - y2);
    sh[9]  = 2.09165007f * y * (3.0f * x2 - y2);
    sh[10] = 10.2469508f * x * y * z;
    sh[11] = 1.62018517f * y * (5.0f * z2 - 1.0f);
    sh[12] = 1.32287566f * (5.0f * z2 * z - 3.0f * z);
    sh[13] = 1.62018517f * x * (5.0f * z2 - 1.0f);
    sh[14] = 5.12347538f * z * (x2 - y2);
    sh[15] = 2.09165007f * x * (x2 - 3.0f * y2);
#pragma unroll
    for (int i = 0; i < 16; i++) g_sh[(size_t)e * 16 + i] = sh[i];
}

// ---------------- K2: h = silu(rb @ rw1 + rb1), rb fused on the fly --------
// tile: 64 edges x 64 cols, K=128 in two chunks of 64. 256 threads, 4x4 reg tile.
__global__ __launch_bounds__(256) void k_gemm1(const float* __restrict__ rw1,
                                               const float* __restrict__ rb1) {
    __shared__ float  sA[64][65];   // [k][row]
    __shared__ float  sW[64][64];   // [k][col]
    __shared__ float2 sG[64];
    int t  = threadIdx.x;
    int e0 = blockIdx.x * 64;
    if (t < 64) sG[t] = g_geo[e0 + t];
    float acc[4][4];
#pragma unroll
    for (int i = 0; i < 4; i++)
#pragma unroll
        for (int j = 0; j < 4; j++) acc[i][j] = 0.0f;
    int kcol = t & 63, rbase = t >> 6;       // A fill
    int jW = t & 63,  kWb = t >> 6;          // W fill
    int r0 = (t >> 4) << 2;                  // compute row group
    int j0 = (t & 15) << 2;                  // compute col group
    for (int kk = 0; kk < 128; kk += 64) {
        __syncthreads();
#pragma unroll
        for (int i = 0; i < 16; i++) {
            int row = rbase + (i << 2);
            float2 gg = sG[row];
            float n = (float)(kk + kcol + 1);
            sA[kcol][row] = gg.y * sinpif(n * gg.x);
        }
#pragma unroll
        for (int i = 0; i < 16; i++) {
            int kr = kWb + (i << 2);
            sW[kr][jW] = rw1[(kk + kr) * 64 + jW];
        }
        __syncthreads();
#pragma unroll 8
        for (int k = 0; k < 64; k++) {
            float a0 = sA[k][r0], a1 = sA[k][r0 + 1], a2 = sA[k][r0 + 2], a3 = sA[k][r0 + 3];
            float4 b = *reinterpret_cast<const float4*>(&sW[k][j0]);
            acc[0][0] = fmaf(a0, b.x, acc[0][0]); acc[0][1] = fmaf(a0, b.y, acc[0][1]);
            acc[0][2] = fmaf(a0, b.z, acc[0][2]); acc[0][3] = fmaf(a0, b.w, acc[0][3]);
            acc[1][0] = fmaf(a1, b.x, acc[1][0]); acc[1][1] = fmaf(a1, b.y, acc[1][1]);
            acc[1][2] = fmaf(a1, b.z, acc[1][2]); acc[1][3] = fmaf(a1, b.w, acc[1][3]);
            acc[2][0] = fmaf(a2, b.x, acc[2][0]); acc[2][1] = fmaf(a2, b.y, acc[2][1]);
            acc[2][2] = fmaf(a2, b.z, acc[2][2]); acc[2][3] = fmaf(a2, b.w, acc[2][3]);
            acc[3][0] = fmaf(a3, b.x, acc[3][0]); acc[3][1] = fmaf(a3, b.y, acc[3][1]);
            acc[3][2] = fmaf(a3, b.z, acc[3][2]); acc[3][3] = fmaf(a3, b.w, acc[3][3]);
        }
    }
    float4 bias = *reinterpret_cast<const float4*>(&rb1[j0]);
#pragma unroll
    for (int i = 0; i < 4; i++) {
        float4 o;
        o.x = siluf(acc[i][0] + bias.x);
        o.y = siluf(acc[i][1] + bias.y);
        o.z = siluf(acc[i][2] + bias.z);
        o.w = siluf(acc[i][3] + bias.w);
        *reinterpret_cast<float4*>(&g_h[(size_t)(e0 + r0 + i) * 64 + j0]) = o;
    }
}

// ---------------- K3: [w_all | ew] = h @ [rw2 | edge_w] + bias -------------
// tile: 64 edges x 128 cols, grid.y = col-block (0..2 -> rw2, 3 -> edge_w)
__global__ __launch_bounds__(256) void k_gemm2(const float* __restrict__ rw2,
                                               const float* __restrict__ rb2,
                                               const float* __restrict__ edge_w,
                                               const float* __restrict__ edge_b) {
    __shared__ float sH[32][65];
    __shared__ float sW2[32][128];
    int t  = threadIdx.x;
    int e0 = blockIdx.x * 64;
    int jb = blockIdx.y;
    float acc[4][8];
#pragma unroll
    for (int i = 0; i < 4; i++)
#pragma unroll
        for (int j = 0; j < 8; j++) acc[i][j] = 0.0f;
    int r0 = (t >> 4) << 2;
    int j0 = (t & 15) << 3;
    int kh = t & 31, rb_ = (t >> 5) << 3;
    int jw = t & 127, kwb = t >> 7;
    for (int kk = 0; kk < 64; kk += 32) {
        __syncthreads();
#pragma unroll
        for (int i = 0; i < 8; i++)
            sH[kh][rb_ + i] = g_h[(size_t)(e0 + rb_ + i) * 64 + kk + kh];
#pragma unroll
        for (int i = 0; i < 16; i++) {
            int kr = kwb + (i << 1);
            sW2[kr][jw] = (jb < 3) ? rw2[(kk + kr) * 384 + jb * 128 + jw]
                                   : edge_w[(kk + kr) * 128 + jw];
        }
        __syncthreads();
#pragma unroll 4
        for (int k = 0; k < 32; k++) {
            float a0 = sH[k][r0], a1 = sH[k][r0 + 1], a2 = sH[k][r0 + 2], a3 = sH[k][r0 + 3];
            float4 b0 = *reinterpret_cast<const float4*>(&sW2[k][j0]);
            float4 b1 = *reinterpret_cast<const float4*>(&sW2[k][j0 + 4]);
            float bv[8] = {b0.x, b0.y, b0.z, b0.w, b1.x, b1.y, b1.z, b1.w};
#pragma unroll
            for (int j = 0; j < 8; j++) {
                acc[0][j] = fmaf(a0, bv[j], acc[0][j]);
                acc[1][j] = fmaf(a1, bv[j], acc[1][j]);
                acc[2][j] = fmaf(a2, bv[j], acc[2][j]);
                acc[3][j] = fmaf(a3, bv[j], acc[3][j]);
            }
        }
    }
    float bias[8];
#pragma unroll
    for (int j = 0; j < 8; j++)
        bias[j] = (jb < 3) ? rb2[jb * 128 + j0 + j] : edge_b[j0 + j];
#pragma unroll
    for (int i = 0; i < 4; i++) {
        int row = e0 + r0 + i;
        float* base = (jb < 3) ? &g_w[(size_t)row * 384 + jb * 128 + j0]
                               : &g_ew[(size_t)row * 128 + j0];
        float4 o0, o1;
        o0.x = acc[i][0] + bias[0]; o0.y = acc[i][1] + bias[1];
        o0.z = acc[i][2] + bias[2]; o0.w = acc[i][3] + bias[3];
        o1.x = acc[i][4] + bias[4]; o1.y = acc[i][5] + bias[5];
        o1.z = acc[i][6] + bias[6]; o1.w = acc[i][7] + bias[7];
        *reinterpret_cast<float4*>(base)     = o0;
        *reinterpret_cast<float4*>(base + 4) = o1;
    }
}

// ---------------- init / zero ----------------------------------------------
__global__ void k_zero_f0() { g_f[0][blockIdx.x * 256 + threadIdx.x] = 0.0f; }
__global__ void k_zero_agg() { g_agg[blockIdx.x * 256 + threadIdx.x] = 0.0f; }
__global__ void k_initf(const float* __restrict__ node_embed,
                        const int* __restrict__ species) {
    int idx = blockIdx.x * 256 + threadIdx.x;   // over N*C
    int n = idx >> 5, c = idx & 31;
    g_f[0][idx] = node_embed[(species[n] << 5) + c];
}

// ---------------- K4: fused message + scatter (atomicAdd) -------------------
__global__ __launch_bounds__(256) void k_scatter(const int* __restrict__ ei,
                                                 int t, int cur) {
    int lane = threadIdx.x & 31;
    int e = blockIdx.x * 8 + (threadIdx.x >> 5);
    int s = ei[e], d = ei[NEDGE + e];
    float sv = g_f[cur][s * C + lane];
    const float* wr = g_w + (size_t)e * 384 + t * 128;
    const float* sh = g_sh + (size_t)e * 16;
    float w0 = wr[lane] * sv;
    atomicAdd(&g_agg[d * C + lane], w0);
    float w1 = wr[32 + lane] * sv;
    float* p1 = &g_agg[F_OFF1 + (d * 3) * C + lane];
#pragma unroll
    for (int m = 0; m < 3; m++) atomicAdd(p1 + m * C, w1 * sh[1 + m]);
    float w2 = wr[64 + lane] * sv;
    float* p2 = &g_agg[F_OFF2 + (d * 5) * C + lane];
#pragma unroll
    for (int m = 0; m < 5; m++) atomicAdd(p2 + m * C, w2 * sh[4 + m]);
    float w3 = wr[96 + lane] * sv;
    float* p3 = &g_agg[F_OFF3 + (d * 7) * C + lane];
#pragma unroll
    for (int m = 0; m < 7; m++) atomicAdd(p3 + m * C, w3 * sh[9 + m]);
}

// ---------------- K5: node update (warp per node) ---------------------------
__global__ __launch_bounds__(256) void k_node(const float* __restrict__ self_w,
                                              const float* __restrict__ msg_w,
                                              const float* __restrict__ gate_w,
                                              int t, int cur) {
    __shared__ float sS[4096];
    __shared__ float sM[4096];
    __shared__ float sG[1024];
    int tid = threadIdx.x;
    for (int i = tid; i < 4096; i += 256) {
        sS[i] = self_w[t * 4096 + i];
        sM[i] = msg_w[t * 4096 + i];
    }
    for (int i = tid; i < 1024; i += 256) sG[i] = gate_w[t * 1024 + i];
    __syncthreads();
    int lane = tid & 31;
    int n = blockIdx.x * 8 + (tid >> 5);
    const float* fin = g_f[cur];
    float* fout = g_f[cur ^ 1];
    // l = 0
    float fv = fin[n * C + lane];
    float av = g_agg[n * C + lane];
    float a0 = 0.0f;
#pragma unroll
    for (int c = 0; c < 32; c++) {
        a0 = fmaf(__shfl_sync(0xffffffffu, fv, c), sS[c * 32 + lane], a0);
        a0 = fmaf(__shfl_sync(0xffffffffu, av, c), sM[c * 32 + lane], a0);
    }
    float ga = 0.0f;
#pragma unroll
    for (int c = 0; c < 32; c++)
        ga = fmaf(__shfl_sync(0xffffffffu, a0, c), sG[c * 32 + lane], ga);
    float gate = 1.0f / (1.0f + expf(-ga));
    fout[n * C + lane] = siluf(a0);
    const int offs[4] = {0, F_OFF1, F_OFF2, F_OFF3};
    const int dls[4]  = {1, 3, 5, 7};
#pragma unroll
    for (int l = 1; l < 4; l++) {
        const float* Ws = sS + l * 1024;
        const float* Wm = sM + l * 1024;
        int dl = dls[l];
        int base = offs[l] + n * dl * C + lane;
        for (int m = 0; m < dl; m++) {
            float fvm = fin[base + m * C];
            float avm = g_agg[base + m * C];
            float a = 0.0f;
#pragma unroll
            for (int c = 0; c < 32; c++) {
                a = fmaf(__shfl_sync(0xffffffffu, fvm, c), Ws[c * 32 + lane], a);
                a = fmaf(__shfl_sync(0xffffffffu, avm, c), Wm[c * 32 + lane], a);
            }
            fout[base + m * C] = a * gate;
        }
    }
}

// ---------------- outputs ---------------------------------------------------
__global__ void k_nodeout(float* __restrict__ out, int cur) {
    int n = blockIdx.x, col = threadIdx.x;
    int l, c, m, dl, off;
    decode_col(col, l, c, m, dl, off);
    out[(size_t)n * 512 + col] = g_f[cur][off + (n * dl + m) * C + c];
}

__global__ void k_edgeout(const int* __restrict__ ei, float* __restrict__ out,
                          int cur) {
    int e = blockIdx.x, col = threadIdx.x;
    int s = ei[e], d = ei[NEDGE + e];
    int l, c, m, dl, off;
    decode_col(col, l, c, m, dl, off);
    const int shb[4] = {0, 1, 4, 9};
    float gv = g_f[cur][s * C + c] + g_f[cur][d * C + c];
    float val = g_ew[(size_t)e * 128 + l * 32 + c] * gv *
                g_sh[(size_t)e * 16 + shb[l] + m];
    out[(size_t)(NNODE + e) * 512 + col] = val;
}

// ---------------- launch ----------------------------------------------------
extern "C" void kernel_launch(void* const* d_in, const int* in_sizes, int n_in,
                              void* d_out, int out_size) {
    const float* pos        = (const float*)d_in[0];
    const float* node_embed = (const float*)d_in[1];
    const float* rw1        = (const float*)d_in[2];
    const float* rb1        = (const float*)d_in[3];
    const float* rw2        = (const float*)d_in[4];
    const float* rb2        = (const float*)d_in[5];
    const float* self_w     = (const float*)d_in[6];
    const float* msg_w      = (const float*)d_in[7];
    const float* gate_w     = (const float*)d_in[8];
    const float* edge_w     = (const float*)d_in[9];
    const float* edge_b     = (const float*)d_in[10];
    const int*   species    = (const int*)d_in[11];
    const int*   ei         = (const int*)d_in[12];
    float* out = (float*)d_out;

    k_geom<<<NEDGE / 256, 256>>>(pos, ei);
    k_gemm1<<<NEDGE / 64, 256>>>(rw1, rb1);
    dim3 g2(NEDGE / 64, 4);
    k_gemm2<<<g2, 256>>>(rw2, rb2, edge_w, edge_b);
    k_zero_f0<<<FTOT / 256, 256>>>();
    k_initf<<<NNODE * C / 256, 256>>>(node_embed, species);

    int cur = 0;
    for (int t = 0; t < 3; t++) {
        k_zero_agg<<<FTOT / 256, 256>>>();
        k_scatter<<<NEDGE / 8, 256>>>(ei, t, cur);
        k_node<<<NNODE / 8, 256>>>(self_w, msg_w, gate_w, t, cur);
        cur ^= 1;
    }

    k_nodeout<<<NNODE, 512>>>(out, cur);
    k_edgeout<<<NEDGE, 512>>>(ei, out, cur);
}

// round 2
// speedup vs baseline: 1.6189x; 1.6189x over previous
#include <cuda_runtime.h>
#include <math.h>

typedef unsigned long long ull;

constexpr int NNODE = 10000;
constexpr int NEDGE = 160000;
constexpr int C = 32;
constexpr int H = 64;
constexpr int F_OFF1 = NNODE * C;        // start of l=1 block
constexpr int F_OFF2 = 4 * NNODE * C;    // start of l=2 block
constexpr int F_OFF3 = 9 * NNODE * C;    // start of l=3 block
constexpr int FTOT   = 16 * NNODE * C;   // total f elements

// ---------------- scratch (device globals) ---------------------------------
__device__ float  g_h [(size_t)NEDGE * H];      // edge hidden (E,64)   [sorted order]
__device__ float  g_w [(size_t)NEDGE * 384];    // w_all (E, L*NL*C)    [sorted order]
__device__ float  g_ew[(size_t)NEDGE * 128];    // edge weights         [sorted order]
__device__ float  g_sh[(size_t)NEDGE * 16];     // spherical harmonics  [sorted order]
__device__ float2 g_geo[NEDGE];                 // (u, env*sqrt(2/RC)/r)[sorted order]
__device__ float  g_f[2][FTOT];                 // node features, double buffered
__device__ int    g_cnt[NNODE];                 // per-dst counts
__device__ int    g_fill[NNODE];                // fill cursors
__device__ int    g_rowstart[NNODE + 1];        // CSR row starts
__device__ int    g_src[NEDGE];                 // permuted src node
__device__ int    g_dst[NEDGE];                 // permuted dst node
__device__ int    g_orig[NEDGE];                // sorted pos -> original edge id

__device__ __forceinline__ float siluf(float x) { return x / (1.0f + expf(-x)); }

__device__ __forceinline__ ull dup2(float a) {
    ull r;
    asm("mov.b64 %0, {%1, %1};" : "=l"(r) : "r"(__float_as_uint(a)));
    return r;
}
__device__ __forceinline__ void ffma2(ull& d, ull a, ull b) {
    asm("fma.rn.f32x2 %0, %1, %2, %0;" : "+l"(d) : "l"(a), "l"(b));
}
__device__ __forceinline__ float2 unpack2(ull v) {
    float2 f;
    asm("mov.b64 {%0, %1}, %2;" : "=f"(f.x), "=f"(f.y) : "l"(v));
    return f;
}

__device__ __forceinline__ void decode_col(int col, int& l, int& c, int& m,
                                           int& dl, int& off) {
    if (col < 32)       { l = 0; c = col;          m = 0;         dl = 1; off = 0;      }
    else if (col < 128) { l = 1; int q = col - 32;  c = q / 3; m = q - 3 * c; dl = 3; off = F_OFF1; }
    else if (col < 288) { l = 2; int q = col - 128; c = q / 5; m = q - 5 * c; dl = 5; off = F_OFF2; }
    else                { l = 3; int q = col - 288; c = q / 7; m = q - 7 * c; dl = 7; off = F_OFF3; }
}

// ---------------- sorting: counting sort by dst ----------------------------
__global__ void k_zero_sort() {
    int i = blockIdx.x * 256 + threadIdx.x;
    if (i < NNODE) { g_cnt[i] = 0; g_fill[i] = 0; }
}
__global__ void k_count(const int* __restrict__ ei) {
    int e = blockIdx.x * 256 + threadIdx.x;
    atomicAdd(&g_cnt[ei[NEDGE + e]], 1);
}
__global__ void k_scan() {   // single block, 1024 threads, 10 elems each
    __shared__ int part[1024];
    int t = threadIdx.x;
    int base = t * 10;
    int vals[10];
    int s = 0;
#pragma unroll
    for (int i = 0; i < 10; i++) {
        int idx = base + i;
        int v = (idx < NNODE) ? g_cnt[idx] : 0;
        vals[i] = s; s += v;
    }
    part[t] = s;
    __syncthreads();
    for (int d = 1; d < 1024; d <<= 1) {
        int v = (t >= d) ? part[t - d] : 0;
        __syncthreads();
        part[t] += v;
        __syncthreads();
    }
    int off = (t == 0) ? 0 : part[t - 1];
#pragma unroll
    for (int i = 0; i < 10; i++) {
        int idx = base + i;
        if (idx < NNODE) g_rowstart[idx] = off + vals[i];
    }
    if (t == 1023) g_rowstart[NNODE] = part[1023];
}

// fill sorted position AND compute geometry + spherical harmonics there
__global__ void k_fillgeom(const float* __restrict__ pos, const int* __restrict__ ei) {
    int e = blockIdx.x * 256 + threadIdx.x;
    int s = ei[e], d = ei[NEDGE + e];
    int p = g_rowstart[d] + atomicAdd(&g_fill[d], 1);
    g_src[p] = s; g_dst[p] = d; g_orig[p] = e;
    float ax = pos[3 * s], ay = pos[3 * s + 1], az = pos[3 * s + 2];
    float bx = pos[3 * d], by = pos[3 * d + 1], bz = pos[3 * d + 2];
    float vx = bx - ax, vy = by - ay, vz = bz - az;
    float r = sqrtf(vx * vx + vy * vy + vz * vz + 1e-12f);
    float u = fminf(r * (1.0f / 5.0f), 1.0f);
    float env = 0.5f * (cospif(u) + 1.0f);
    g_geo[p] = make_float2(u, env * 0.63245553203f / r);
    float inv = 1.0f / r;
    float x = vx * inv, y = vy * inv, z = vz * inv;
    float x2 = x * x, y2 = y * y, z2 = z * z;
    float4* shp = reinterpret_cast<float4*>(g_sh + (size_t)p * 16);
    shp[0] = make_float4(1.0f, 1.7320508f * x, 1.7320508f * y, 1.7320508f * z);
    shp[1] = make_float4(3.87298335f * x * y, 3.87298335f * y * z,
                         1.11803399f * (3.0f * z2 - 1.0f), 3.87298335f * x * z);
    shp[2] = make_float4(1.93649167f * (x2 - y2),
                         2.09165007f * y * (3.0f * x2 - y2),
                         10.2469508f * x * y * z,
                         1.62018517f * y * (5.0f * z2 - 1.0f));
    shp[3] = make_float4(1.32287566f * (5.0f * z2 * z - 3.0f * z),
                         1.62018517f * x * (5.0f * z2 - 1.0f),
                         5.12347538f * z * (x2 - y2),
                         2.09165007f * x * (x2 - 3.0f * y2));
}

// ---------------- K2: h = silu(rb @ rw1 + rb1), rb fused, FFMA2 ------------
__global__ __launch_bounds__(256) void k_gemm1(const float* __restrict__ rw1,
                                               const float* __restrict__ rb1) {
    __shared__ float  sA[64][65];   // [k][row] - stride 65 keeps write conflict-free
    __shared__ float  sW[64][64];   // [k][col]
    __shared__ float2 sG[64];
    int t  = threadIdx.x;
    int e0 = blockIdx.x * 64;
    if (t < 64) sG[t] = g_geo[e0 + t];
    ull acc[4][2];
#pragma unroll
    for (int i = 0; i < 4; i++) { acc[i][0] = 0ull; acc[i][1] = 0ull; }
    int kcol = t & 63, rbase = t >> 6;
    int jW = t & 63,  kWb = t >> 6;
    int r0 = (t >> 4) << 2;
    int j0 = (t & 15) << 2;
    for (int kk = 0; kk < 128; kk += 64) {
        __syncthreads();
#pragma unroll
        for (int i = 0; i < 16; i++) {
            int row = rbase + (i << 2);
            float2 gg = sG[row];
            float n = (float)(kk + kcol + 1);
            sA[kcol][row] = gg.y * sinpif(n * gg.x);
        }
#pragma unroll
        for (int i = 0; i < 16; i++) {
            int kr = kWb + (i << 2);
            sW[kr][jW] = rw1[(kk + kr) * 64 + jW];
        }
        __syncthreads();
#pragma unroll 8
        for (int k = 0; k < 64; k++) {
            ull A0 = dup2(sA[k][r0]);
            ull A1 = dup2(sA[k][r0 + 1]);
            ull A2 = dup2(sA[k][r0 + 2]);
            ull A3 = dup2(sA[k][r0 + 3]);
            const ull* bp = reinterpret_cast<const ull*>(&sW[k][j0]);
            ull b0 = bp[0], b1 = bp[1];
            ffma2(acc[0][0], A0, b0); ffma2(acc[0][1], A0, b1);
            ffma2(acc[1][0], A1, b0); ffma2(acc[1][1], A1, b1);
            ffma2(acc[2][0], A2, b0); ffma2(acc[2][1], A2, b1);
            ffma2(acc[3][0], A3, b0); ffma2(acc[3][1], A3, b1);
        }
    }
    float4 bias = *reinterpret_cast<const float4*>(&rb1[j0]);
#pragma unroll
    for (int i = 0; i < 4; i++) {
        float2 lo = unpack2(acc[i][0]), hi = unpack2(acc[i][1]);
        float4 o;
        o.x = siluf(lo.x + bias.x); o.y = siluf(lo.y + bias.y);
        o.z = siluf(hi.x + bias.z); o.w = siluf(hi.y + bias.w);
        *reinterpret_cast<float4*>(&g_h[(size_t)(e0 + r0 + i) * 64 + j0]) = o;
    }
}

// ---------------- K3: [w_all | ew] = h @ [rw2 | edge_w] + bias, FFMA2 ------
__global__ __launch_bounds__(256) void k_gemm2(const float* __restrict__ rw2,
                                               const float* __restrict__ rb2,
                                               const float* __restrict__ edge_w,
                                               const float* __restrict__ edge_b) {
    __shared__ float sH[32][65];
    __shared__ float sW2[32][128];
    int t  = threadIdx.x;
    int e0 = blockIdx.x * 64;
    int jb = blockIdx.y;
    ull acc[4][4];
#pragma unroll
    for (int i = 0; i < 4; i++)
#pragma unroll
        for (int j = 0; j < 4; j++) acc[i][j] = 0ull;
    int r0 = (t >> 4) << 2;
    int j0 = (t & 15) << 3;
    int kh = t & 31, rb_ = (t >> 5) << 3;
    int jw = t & 127, kwb = t >> 7;
    for (int kk = 0; kk < 64; kk += 32) {
        __syncthreads();
#pragma unroll
        for (int i = 0; i < 8; i++)
            sH[kh][rb_ + i] = g_h[(size_t)(e0 + rb_ + i) * 64 + kk + kh];
#pragma unroll
        for (int i = 0; i < 16; i++) {
            int kr = kwb + (i << 1);
            sW2[kr][jw] = (jb < 3) ? rw2[(kk + kr) * 384 + jb * 128 + jw]
                                   : edge_w[(kk + kr) * 128 + jw];
        }
        __syncthreads();
#pragma unroll 4
        for (int k = 0; k < 32; k++) {
            ull A0 = dup2(sH[k][r0]);
            ull A1 = dup2(sH[k][r0 + 1]);
            ull A2 = dup2(sH[k][r0 + 2]);
            ull A3 = dup2(sH[k][r0 + 3]);
            const ull* bp = reinterpret_cast<const ull*>(&sW2[k][j0]);
            ull b0 = bp[0], b1 = bp[1], b2 = bp[2], b3 = bp[3];
            ffma2(acc[0][0], A0, b0); ffma2(acc[0][1], A0, b1);
            ffma2(acc[0][2], A0, b2); ffma2(acc[0][3], A0, b3);
            ffma2(acc[1][0], A1, b0); ffma2(acc[1][1], A1, b1);
            ffma2(acc[1][2], A1, b2); ffma2(acc[1][3], A1, b3);
            ffma2(acc[2][0], A2, b0); ffma2(acc[2][1], A2, b1);
            ffma2(acc[2][2], A2, b2); ffma2(acc[2][3], A2, b3);
            ffma2(acc[3][0], A3, b0); ffma2(acc[3][1], A3, b1);
            ffma2(acc[3][2], A3, b2); ffma2(acc[3][3], A3, b3);
        }
    }
    float bias[8];
#pragma unroll
    for (int j = 0; j < 8; j++)
        bias[j] = (jb < 3) ? rb2[jb * 128 + j0 + j] : edge_b[j0 + j];
#pragma unroll
    for (int i = 0; i < 4; i++) {
        int row = e0 + r0 + i;
        float* base = (jb < 3) ? &g_w[(size_t)row * 384 + jb * 128 + j0]
                               : &g_ew[(size_t)row * 128 + j0];
        float2 p0 = unpack2(acc[i][0]), p1 = unpack2(acc[i][1]);
        float2 p2 = unpack2(acc[i][2]), p3 = unpack2(acc[i][3]);
        float4 o0 = make_float4(p0.x + bias[0], p0.y + bias[1], p1.x + bias[2], p1.y + bias[3]);
        float4 o1 = make_float4(p2.x + bias[4], p2.y + bias[5], p3.x + bias[6], p3.y + bias[7]);
        *reinterpret_cast<float4*>(base)     = o0;
        *reinterpret_cast<float4*>(base + 4) = o1;
    }
}

// ---------------- init f[0]: l0 = embed[species], l>=1 = 0 ------------------
__global__ void k_initf(const float* __restrict__ node_embed,
                        const int* __restrict__ species) {
    int i4 = blockIdx.x * 256 + threadIdx.x;   // over FTOT/4
    int idx = i4 * 4;
    float4 v;
    if (idx < NNODE * C) {
        int n = idx >> 5, c = idx & 31;
        v = *reinterpret_cast<const float4*>(&node_embed[(species[n] << 5) + c]);
    } else {
        v = make_float4(0.f, 0.f, 0.f, 0.f);
    }
    *reinterpret_cast<float4*>(&g_f[0][idx]) = v;
}

// ---------------- K4: fused gather-aggregate + node update ------------------
// warp per node, lane = channel. CSR rows are contiguous per dst.
__global__ __launch_bounds__(256) void k_msgnode(const float* __restrict__ self_w,
                                                 const float* __restrict__ msg_w,
                                                 const float* __restrict__ gate_w,
                                                 int t, int cur,
                                                 float* __restrict__ out) {
    __shared__ float sS[4096];
    __shared__ float sM[4096];
    __shared__ float sG[1024];
    int tid = threadIdx.x;
    for (int i = tid; i < 4096; i += 256) {
        sS[i] = self_w[t * 4096 + i];
        sM[i] = msg_w[t * 4096 + i];
    }
    for (int i = tid; i < 1024; i += 256) sG[i] = gate_w[t * 1024 + i];
    __syncthreads();
    int lane = tid & 31;
    int n = blockIdx.x * 8 + (tid >> 5);
    const float* fin = g_f[cur];
    float* fout = g_f[cur ^ 1];

    float acc[16];
#pragma unroll
    for (int i = 0; i < 16; i++) acc[i] = 0.0f;
    int row0 = g_rowstart[n], row1 = g_rowstart[n + 1];
    for (int row = row0; row < row1; row++) {
        float sv = fin[g_src[row] * C + lane];
        const float* wr = g_w + (size_t)row * 384 + t * 128;
        float w0 = wr[lane] * sv;
        float w1 = wr[32 + lane] * sv;
        float w2 = wr[64 + lane] * sv;
        float w3 = wr[96 + lane] * sv;
        const float4* shp = reinterpret_cast<const float4*>(g_sh + (size_t)row * 16);
        float4 s0 = shp[0], s1 = shp[1], s2 = shp[2], s3 = shp[3];
        acc[0]  += w0;                         // sh[0] == 1
        acc[1]  = fmaf(w1, s0.y, acc[1]);
        acc[2]  = fmaf(w1, s0.z, acc[2]);
        acc[3]  = fmaf(w1, s0.w, acc[3]);
        acc[4]  = fmaf(w2, s1.x, acc[4]);
        acc[5]  = fmaf(w2, s1.y, acc[5]);
        acc[6]  = fmaf(w2, s1.z, acc[6]);
        acc[7]  = fmaf(w2, s1.w, acc[7]);
        acc[8]  = fmaf(w2, s2.x, acc[8]);
        acc[9]  = fmaf(w3, s2.y, acc[9]);
        acc[10] = fmaf(w3, s2.z, acc[10]);
        acc[11] = fmaf(w3, s2.w, acc[11]);
        acc[12] = fmaf(w3, s3.x, acc[12]);
        acc[13] = fmaf(w3, s3.y, acc[13]);
        acc[14] = fmaf(w3, s3.z, acc[14]);
        acc[15] = fmaf(w3, s3.w, acc[15]);
    }

    // l = 0 update + gate
    float fv = fin[n * C + lane];
    float a0 = 0.0f;
#pragma unroll
    for (int c = 0; c < 32; c++) {
        a0 = fmaf(__shfl_sync(0xffffffffu, fv, c), sS[c * 32 + lane], a0);
        a0 = fmaf(__shfl_sync(0xffffffffu, acc[0], c), sM[c * 32 + lane], a0);
    }
    float ga = 0.0f;
#pragma unroll
    for (int c = 0; c < 32; c++)
        ga = fmaf(__shfl_sync(0xffffffffu, a0, c), sG[c * 32 + lane], ga);
    float gate = 1.0f / (1.0f + expf(-ga));
    float s0v = siluf(a0);
    fout[n * C + lane] = s0v;
    if (t == 2) out[(size_t)n * 512 + lane] = s0v;

    const int offs[4]    = {0, F_OFF1, F_OFF2, F_OFF3};
    const int dls[4]     = {1, 3, 5, 7};
    const int accb[4]    = {0, 1, 4, 9};
    const int colb[4]    = {0, 32, 128, 288};
#pragma unroll
    for (int l = 1; l < 4; l++) {
        const float* Ws = sS + l * 1024;
        const float* Wm = sM + l * 1024;
        int dl = dls[l];
        int base = offs[l] + n * dl * C + lane;
        for (int m = 0; m < dl; m++) {
            float fvm = fin[base + m * C];
            float avm = acc[accb[l] + m];
            float a = 0.0f;
#pragma unroll
            for (int c = 0; c < 32; c++) {
                a = fmaf(__shfl_sync(0xffffffffu, fvm, c), Ws[c * 32 + lane], a);
                a = fmaf(__shfl_sync(0xffffffffu, avm, c), Wm[c * 32 + lane], a);
            }
            float res = a * gate;
            if (t < 2) fout[base + m * C] = res;
            else       out[(size_t)n * 512 + colb[l] + lane * dl + m] = res;
        }
    }
}

// ---------------- edge output -----------------------------------------------
__global__ void k_edgeout(float* __restrict__ out, int cur) {
    int e = blockIdx.x, col = threadIdx.x;
    int l, c, m, dl, off;
    decode_col(col, l, c, m, dl, off);
    const int shb[4] = {0, 1, 4, 9};
    int s = g_src[e], d = g_dst[e];
    float gv = g_f[cur][s * C + c] + g_f[cur][d * C + c];
    float val = g_ew[(size_t)e * 128 + l * 32 + c] * gv *
                g_sh[(size_t)e * 16 + shb[l] + m];
    out[(size_t)(NNODE + g_orig[e]) * 512 + col] = val;
}

// ---------------- launch ----------------------------------------------------
extern "C" void kernel_launch(void* const* d_in, const int* in_sizes, int n_in,
                              void* d_out, int out_size) {
    const float* pos        = (const float*)d_in[0];
    const float* node_embed = (const float*)d_in[1];
    const float* rw1        = (const float*)d_in[2];
    const float* rb1        = (const float*)d_in[3];
    const float* rw2        = (const float*)d_in[4];
    const float* rb2        = (const float*)d_in[5];
    const float* self_w     = (const float*)d_in[6];
    const float* msg_w      = (const float*)d_in[7];
    const float* gate_w     = (const float*)d_in[8];
    const float* edge_w     = (const float*)d_in[9];
    const float* edge_b     = (const float*)d_in[10];
    const int*   species    = (const int*)d_in[11];
    const int*   ei         = (const int*)d_in[12];
    float* out = (float*)d_out;

    k_zero_sort<<<(NNODE + 255) / 256, 256>>>();          // 0
    k_count<<<NEDGE / 256, 256>>>(ei);                    // 1
    k_scan<<<1, 1024>>>();                                // 2
    k_fillgeom<<<NEDGE / 256, 256>>>(pos, ei);            // 3
    k_gemm1<<<NEDGE / 64, 256>>>(rw1, rb1);               // 4
    dim3 g2(NEDGE / 64, 4);
    k_gemm2<<<g2, 256>>>(rw2, rb2, edge_w, edge_b);       // 5  <- ncu -s 5 lands here
    k_initf<<<FTOT / 4 / 256, 256>>>(node_embed, species);

    int cur = 0;
    for (int t = 0; t < 3; t++) {
        k_msgnode<<<NNODE / 8, 256>>>(self_w, msg_w, gate_w, t, cur, out);
        cur ^= 1;
    }

    k_edgeout<<<NEDGE, 512>>>(out, cur);
}

// round 3
// speedup vs baseline: 2.2052x; 1.3622x over previous
#include <cuda_runtime.h>
#include <math.h>

typedef unsigned long long ull;

constexpr int NNODE = 10000;
constexpr int NEDGE = 160000;
constexpr int C = 32;
constexpr int H = 64;
constexpr int F_OFF1 = NNODE * C;
constexpr int F_OFF2 = 4 * NNODE * C;
constexpr int F_OFF3 = 9 * NNODE * C;
constexpr int FTOT   = 16 * NNODE * C;

// ---------------- scratch ---------------------------------------------------
__device__ float  g_h [(size_t)NEDGE * H];
__device__ float  g_w [(size_t)NEDGE * 384];
__device__ float  g_ew[(size_t)NEDGE * 128];
__device__ float  g_sh[(size_t)NEDGE * 16];
__device__ float2 g_geo[NEDGE];
__device__ float  g_f[2][FTOT];
__device__ int    g_cnt[NNODE];
__device__ int    g_fill[NNODE];
__device__ int    g_rowstart[NNODE + 1];
__device__ int    g_src[NEDGE];
__device__ int    g_dst[NEDGE];
__device__ int    g_orig[NEDGE];

__device__ __forceinline__ float siluf(float x) { return x / (1.0f + expf(-x)); }

__device__ __forceinline__ ull dup2(float a) {
    ull r;
    asm("mov.b64 %0, {%1, %1};" : "=l"(r) : "r"(__float_as_uint(a)));
    return r;
}
__device__ __forceinline__ void ffma2(ull& d, ull a, ull b) {
    asm("fma.rn.f32x2 %0, %1, %2, %0;" : "+l"(d) : "l"(a), "l"(b));
}
__device__ __forceinline__ float2 unpack2(ull v) {
    float2 f;
    asm("mov.b64 {%0, %1}, %2;" : "=f"(f.x), "=f"(f.y) : "l"(v));
    return f;
}

// ---------------- sorting: counting sort by dst ----------------------------
__global__ void k_zero_sort() {
    int i = blockIdx.x * 256 + threadIdx.x;
    if (i < NNODE) { g_cnt[i] = 0; g_fill[i] = 0; }
}
__global__ void k_count(const int* __restrict__ ei) {
    int e = blockIdx.x * 256 + threadIdx.x;
    atomicAdd(&g_cnt[ei[NEDGE + e]], 1);
}
__global__ void k_scan() {
    __shared__ int part[1024];
    int t = threadIdx.x;
    int base = t * 10;
    int vals[10];
    int s = 0;
#pragma unroll
    for (int i = 0; i < 10; i++) {
        int idx = base + i;
        int v = (idx < NNODE) ? g_cnt[idx] : 0;
        vals[i] = s; s += v;
    }
    part[t] = s;
    __syncthreads();
    for (int d = 1; d < 1024; d <<= 1) {
        int v = (t >= d) ? part[t - d] : 0;
        __syncthreads();
        part[t] += v;
        __syncthreads();
    }
    int off = (t == 0) ? 0 : part[t - 1];
#pragma unroll
    for (int i = 0; i < 10; i++) {
        int idx = base + i;
        if (idx < NNODE) g_rowstart[idx] = off + vals[i];
    }
    if (t == 1023) g_rowstart[NNODE] = part[1023];
}

__global__ void k_fillgeom(const float* __restrict__ pos, const int* __restrict__ ei) {
    int e = blockIdx.x * 256 + threadIdx.x;
    int s = ei[e], d = ei[NEDGE + e];
    int p = g_rowstart[d] + atomicAdd(&g_fill[d], 1);
    g_src[p] = s; g_dst[p] = d; g_orig[p] = e;
    float ax = pos[3 * s], ay = pos[3 * s + 1], az = pos[3 * s + 2];
    float bx = pos[3 * d], by = pos[3 * d + 1], bz = pos[3 * d + 2];
    float vx = bx - ax, vy = by - ay, vz = bz - az;
    float r = sqrtf(vx * vx + vy * vy + vz * vz + 1e-12f);
    float u = fminf(r * (1.0f / 5.0f), 1.0f);
    float env = 0.5f * (cospif(u) + 1.0f);
    g_geo[p] = make_float2(u, env * 0.63245553203f / r);
    float inv = 1.0f / r;
    float x = vx * inv, y = vy * inv, z = vz * inv;
    float x2 = x * x, y2 = y * y, z2 = z * z;
    float4* shp = reinterpret_cast<float4*>(g_sh + (size_t)p * 16);
    shp[0] = make_float4(1.0f, 1.7320508f * x, 1.7320508f * y, 1.7320508f * z);
    shp[1] = make_float4(3.87298335f * x * y, 3.87298335f * y * z,
                         1.11803399f * (3.0f * z2 - 1.0f), 3.87298335f * x * z);
    shp[2] = make_float4(1.93649167f * (x2 - y2),
                         2.09165007f * y * (3.0f * x2 - y2),
                         10.2469508f * x * y * z,
                         1.62018517f * y * (5.0f * z2 - 1.0f));
    shp[3] = make_float4(1.32287566f * (5.0f * z2 * z - 3.0f * z),
                         1.62018517f * x * (5.0f * z2 - 1.0f),
                         5.12347538f * z * (x2 - y2),
                         2.09165007f * x * (x2 - 3.0f * y2));
}

// ---------------- K2: h = silu(rb @ rw1 + rb1), rb fused, FFMA2 ------------
__global__ __launch_bounds__(256) void k_gemm1(const float* __restrict__ rw1,
                                               const float* __restrict__ rb1) {
    __shared__ float  sA[64][65];
    __shared__ float  sW[64][64];
    __shared__ float2 sG[64];
    int t  = threadIdx.x;
    int e0 = blockIdx.x * 64;
    if (t < 64) sG[t] = g_geo[e0 + t];
    ull acc[4][2];
#pragma unroll
    for (int i = 0; i < 4; i++) { acc[i][0] = 0ull; acc[i][1] = 0ull; }
    int kcol = t & 63, rbase = t >> 6;
    int jW = t & 63,  kWb = t >> 6;
    int r0 = (t >> 4) << 2;
    int j0 = (t & 15) << 2;
    for (int kk = 0; kk < 128; kk += 64) {
        __syncthreads();
#pragma unroll
        for (int i = 0; i < 16; i++) {
            int row = rbase + (i << 2);
            float2 gg = sG[row];
            float n = (float)(kk + kcol + 1);
            sA[kcol][row] = gg.y * sinpif(n * gg.x);
        }
#pragma unroll
        for (int i = 0; i < 16; i++) {
            int kr = kWb + (i << 2);
            sW[kr][jW] = rw1[(kk + kr) * 64 + jW];
        }
        __syncthreads();
#pragma unroll 8
        for (int k = 0; k < 64; k++) {
            ull A0 = dup2(sA[k][r0]);
            ull A1 = dup2(sA[k][r0 + 1]);
            ull A2 = dup2(sA[k][r0 + 2]);
            ull A3 = dup2(sA[k][r0 + 3]);
            const ull* bp = reinterpret_cast<const ull*>(&sW[k][j0]);
            ull b0 = bp[0], b1 = bp[1];
            ffma2(acc[0][0], A0, b0); ffma2(acc[0][1], A0, b1);
            ffma2(acc[1][0], A1, b0); ffma2(acc[1][1], A1, b1);
            ffma2(acc[2][0], A2, b0); ffma2(acc[2][1], A2, b1);
            ffma2(acc[3][0], A3, b0); ffma2(acc[3][1], A3, b1);
        }
    }
    float4 bias = *reinterpret_cast<const float4*>(&rb1[j0]);
#pragma unroll
    for (int i = 0; i < 4; i++) {
        float2 lo = unpack2(acc[i][0]), hi = unpack2(acc[i][1]);
        float4 o;
        o.x = siluf(lo.x + bias.x); o.y = siluf(lo.y + bias.y);
        o.z = siluf(hi.x + bias.z); o.w = siluf(hi.y + bias.w);
        *reinterpret_cast<float4*>(&g_h[(size_t)(e0 + r0 + i) * 64 + j0]) = o;
    }
}

// ---------------- K3: [w_all | ew] = h @ [rw2 | edge_w] + bias -------------
// 64 rows x 256 cols per block; warp = 64 rows x 32 cols (2 rows/lane, B warp-uniform)
__global__ __launch_bounds__(256) void k_gemm2(const float* __restrict__ rw2,
                                               const float* __restrict__ rb2,
                                               const float* __restrict__ edge_w,
                                               const float* __restrict__ edge_b) {
    __shared__ float sH[32][66];     // [k][row], 66 keeps LDS.64 8B-aligned
    __shared__ float sW2[32][256];   // [k][col]
    int t  = threadIdx.x;
    int e0 = blockIdx.x * 64;
    int cb = blockIdx.y << 8;        // column base in 512-wide concat [w(384)|ew(128)]
    int lane = t & 31;
    int r0 = lane << 1;              // 2 consecutive rows per lane
    int j0 = (t >> 5) << 5;          // 32 cols per warp (warp-uniform)
    ull acc[2][16];
#pragma unroll
    for (int i = 0; i < 2; i++)
#pragma unroll
        for (int j = 0; j < 16; j++) acc[i][j] = 0ull;
    int kh = t & 31, rb_ = (t >> 5) << 3;
    int colg = cb + t;
    for (int kk = 0; kk < 64; kk += 32) {
        __syncthreads();
#pragma unroll
        for (int i = 0; i < 8; i++)
            sH[kh][rb_ + i] = g_h[(size_t)(e0 + rb_ + i) * 64 + kk + kh];
#pragma unroll
        for (int kr = 0; kr < 32; kr++) {
            sW2[kr][t] = (colg < 384) ? rw2[(kk + kr) * 384 + colg]
                                      : edge_w[(kk + kr) * 128 + colg - 384];
        }
        __syncthreads();
#pragma unroll
        for (int k = 0; k < 32; k++) {
            ull a01 = *reinterpret_cast<const ull*>(&sH[k][r0]);
            float2 af = unpack2(a01);
            ull A0 = dup2(af.x), A1 = dup2(af.y);
            const ull* bp = reinterpret_cast<const ull*>(&sW2[k][j0]);
#pragma unroll
            for (int j = 0; j < 16; j++) {
                ull b = bp[j];
                ffma2(acc[0][j], A0, b);
                ffma2(acc[1][j], A1, b);
            }
        }
    }
    bool inw = (cb + j0) < 384;
    const float* bsrc = inw ? (rb2 + cb + j0) : (edge_b + cb + j0 - 384);
#pragma unroll
    for (int i = 0; i < 2; i++) {
        int row = e0 + r0 + i;
        float* base = inw ? (g_w + (size_t)row * 384 + cb + j0)
                          : (g_ew + (size_t)row * 128 + cb + j0 - 384);
#pragma unroll
        for (int j = 0; j < 8; j++) {
            float2 p0 = unpack2(acc[i][2 * j]);
            float2 p1 = unpack2(acc[i][2 * j + 1]);
            float4 o = make_float4(p0.x + bsrc[4 * j],     p0.y + bsrc[4 * j + 1],
                                   p1.x + bsrc[4 * j + 2], p1.y + bsrc[4 * j + 3]);
            *reinterpret_cast<float4*>(base + 4 * j) = o;
        }
    }
}

// ---------------- init f[0] -------------------------------------------------
__global__ void k_initf(const float* __restrict__ node_embed,
                        const int* __restrict__ species) {
    int i4 = blockIdx.x * 256 + threadIdx.x;
    int idx = i4 * 4;
    float4 v;
    if (idx < NNODE * C) {
        int n = idx >> 5, c = idx & 31;
        v = *reinterpret_cast<const float4*>(&node_embed[(species[n] << 5) + c]);
    } else {
        v = make_float4(0.f, 0.f, 0.f, 0.f);
    }
    *reinterpret_cast<float4*>(&g_f[0][idx]) = v;
}

// ---------------- K4: fused gather-aggregate + node update ------------------
__global__ __launch_bounds__(256) void k_msgnode(const float* __restrict__ self_w,
                                                 const float* __restrict__ msg_w,
                                                 const float* __restrict__ gate_w,
                                                 int t, int cur,
                                                 float* __restrict__ out) {
    __shared__ float sS[4096];
    __shared__ float sM[4096];
    __shared__ float sG[1024];
    int tid = threadIdx.x;
    for (int i = tid; i < 4096; i += 256) {
        sS[i] = self_w[t * 4096 + i];
        sM[i] = msg_w[t * 4096 + i];
    }
    for (int i = tid; i < 1024; i += 256) sG[i] = gate_w[t * 1024 + i];
    __syncthreads();
    int lane = tid & 31;
    int n = blockIdx.x * 8 + (tid >> 5);
    const float* fin = g_f[cur];
    float* fout = g_f[cur ^ 1];

    float acc[16];
#pragma unroll
    for (int i = 0; i < 16; i++) acc[i] = 0.0f;
    int row0 = g_rowstart[n], row1 = g_rowstart[n + 1];
#pragma unroll 2
    for (int row = row0; row < row1; row++) {
        float sv = fin[g_src[row] * C + lane];
        const float* wr = g_w + (size_t)row * 384 + t * 128;
        float w0 = wr[lane] * sv;
        float w1 = wr[32 + lane] * sv;
        float w2 = wr[64 + lane] * sv;
        float w3 = wr[96 + lane] * sv;
        const float4* shp = reinterpret_cast<const float4*>(g_sh + (size_t)row * 16);
        float4 s0 = shp[0], s1 = shp[1], s2 = shp[2], s3 = shp[3];
        acc[0]  += w0;
        acc[1]  = fmaf(w1, s0.y, acc[1]);
        acc[2]  = fmaf(w1, s0.z, acc[2]);
        acc[3]  = fmaf(w1, s0.w, acc[3]);
        acc[4]  = fmaf(w2, s1.x, acc[4]);
        acc[5]  = fmaf(w2, s1.y, acc[5]);
        acc[6]  = fmaf(w2, s1.z, acc[6]);
        acc[7]  = fmaf(w2, s1.w, acc[7]);
        acc[8]  = fmaf(w2, s2.x, acc[8]);
        acc[9]  = fmaf(w3, s2.y, acc[9]);
        acc[10] = fmaf(w3, s2.z, acc[10]);
        acc[11] = fmaf(w3, s2.w, acc[11]);
        acc[12] = fmaf(w3, s3.x, acc[12]);
        acc[13] = fmaf(w3, s3.y, acc[13]);
        acc[14] = fmaf(w3, s3.z, acc[14]);
        acc[15] = fmaf(w3, s3.w, acc[15]);
    }

    float fv = fin[n * C + lane];
    float a0 = 0.0f;
#pragma unroll
    for (int c = 0; c < 32; c++) {
        a0 = fmaf(__shfl_sync(0xffffffffu, fv, c), sS[c * 32 + lane], a0);
        a0 = fmaf(__shfl_sync(0xffffffffu, acc[0], c), sM[c * 32 + lane], a0);
    }
    float ga = 0.0f;
#pragma unroll
    for (int c = 0; c < 32; c++)
        ga = fmaf(__shfl_sync(0xffffffffu, a0, c), sG[c * 32 + lane], ga);
    float gate = 1.0f / (1.0f + expf(-ga));
    float s0v = siluf(a0);
    fout[n * C + lane] = s0v;
    if (t == 2) out[(size_t)n * 512 + lane] = s0v;

    const int offs[4] = {0, F_OFF1, F_OFF2, F_OFF3};
    const int dls[4]  = {1, 3, 5, 7};
    const int accb[4] = {0, 1, 4, 9};
    const int colb[4] = {0, 32, 128, 288};
#pragma unroll
    for (int l = 1; l < 4; l++) {
        const float* Ws = sS + l * 1024;
        const float* Wm = sM + l * 1024;
        int dl = dls[l];
        int base = offs[l] + n * dl * C + lane;
        for (int m = 0; m < dl; m++) {
            float fvm = fin[base + m * C];
            float avm = acc[accb[l] + m];
            float a = 0.0f;
#pragma unroll
            for (int c = 0; c < 32; c++) {
                a = fmaf(__shfl_sync(0xffffffffu, fvm, c), Ws[c * 32 + lane], a);
                a = fmaf(__shfl_sync(0xffffffffu, avm, c), Wm[c * 32 + lane], a);
            }
            float res = a * gate;
            if (t < 2) fout[base + m * C] = res;
            else       out[(size_t)n * 512 + colb[l] + lane * dl + m] = res;
        }
    }
}

// ---------------- edge output: warp per edge, lane = channel ----------------
__global__ __launch_bounds__(256) void k_edgeout(float* __restrict__ out, int cur) {
    int lane = threadIdx.x & 31;
    int e = blockIdx.x * 8 + (threadIdx.x >> 5);
    int s = g_src[e], d = g_dst[e];
    const float* f0 = g_f[cur];
    float gv = f0[s * C + lane] + f0[d * C + lane];
    const float* ewp = g_ew + (size_t)e * 128;
    float ew0 = ewp[lane], ew1 = ewp[32 + lane], ew2 = ewp[64 + lane], ew3 = ewp[96 + lane];
    const float4* shp = reinterpret_cast<const float4*>(g_sh + (size_t)e * 16);
    float4 s0 = shp[0], s1 = shp[1], s2 = shp[2], s3 = shp[3];
    float* base = out + (size_t)(NNODE + g_orig[e]) * 512;
    base[lane] = ew0 * gv;
    float w1 = ew1 * gv;
    float* p1 = base + 32 + lane * 3;
    p1[0] = w1 * s0.y; p1[1] = w1 * s0.z; p1[2] = w1 * s0.w;
    float w2 = ew2 * gv;
    float* p2 = base + 128 + lane * 5;
    p2[0] = w2 * s1.x; p2[1] = w2 * s1.y; p2[2] = w2 * s1.z;
    p2[3] = w2 * s1.w; p2[4] = w2 * s2.x;
    float w3 = ew3 * gv;
    float* p3 = base + 288 + lane * 7;
    p3[0] = w3 * s2.y; p3[1] = w3 * s2.z; p3[2] = w3 * s2.w;
    p3[3] = w3 * s3.x; p3[4] = w3 * s3.y; p3[5] = w3 * s3.z; p3[6] = w3 * s3.w;
}

// ---------------- launch ----------------------------------------------------
extern "C" void kernel_launch(void* const* d_in, const int* in_sizes, int n_in,
                              void* d_out, int out_size) {
    const float* pos        = (const float*)d_in[0];
    const float* node_embed = (const float*)d_in[1];
    const float* rw1        = (const float*)d_in[2];
    const float* rb1        = (const float*)d_in[3];
    const float* rw2        = (const float*)d_in[4];
    const float* rb2        = (const float*)d_in[5];
    const float* self_w     = (const float*)d_in[6];
    const float* msg_w      = (const float*)d_in[7];
    const float* gate_w     = (const float*)d_in[8];
    const float* edge_w     = (const float*)d_in[9];
    const float* edge_b     = (const float*)d_in[10];
    const int*   species    = (const int*)d_in[11];
    const int*   ei         = (const int*)d_in[12];
    float* out = (float*)d_out;

    k_zero_sort<<<(NNODE + 255) / 256, 256>>>();
    k_count<<<NEDGE / 256, 256>>>(ei);
    k_scan<<<1, 1024>>>();
    k_fillgeom<<<NEDGE / 256, 256>>>(pos, ei);
    k_gemm1<<<NEDGE / 64, 256>>>(rw1, rb1);
    dim3 g2(NEDGE / 64, 2);
    k_gemm2<<<g2, 256>>>(rw2, rb2, edge_w, edge_b);
    k_initf<<<FTOT / 4 / 256, 256>>>(node_embed, species);

    int cur = 0;
    for (int t = 0; t < 3; t++) {
        k_msgnode<<<NNODE / 8, 256>>>(self_w, msg_w, gate_w, t, cur, out);
        cur ^= 1;
    }

    k_edgeout<<<NEDGE / 8, 256>>>(out, cur);
}